// round 2
// baseline (speedup 1.0000x reference)
#include <cuda_runtime.h>
#include <cuda_bf16.h>
#include <math_constants.h>

// Problem constants
#define B        256
#define N_IN     4096     // W1 rows / x cols
#define N_MID    4096     // W1 cols / W2 rows
#define N_OUT    1024     // W3 cols / output cols

// Scratch routing tables (device globals — no allocation allowed)
__device__ int g_dest1[N_IN];
__device__ int g_dest2[N_MID];
__device__ int g_dest3[N_MID];   // W3 has 4096 rows
__device__ int g_route[N_IN];

// ---------------------------------------------------------------------------
// Row-argmax: one block (128 threads) per row, float4-vectorized streaming
// read, first-max tie-break (smaller index wins) to match jnp.argmax.
// ---------------------------------------------------------------------------
__device__ __forceinline__ void amax_combine(float& v, int& i, float ov, int oi) {
    if (ov > v || (ov == v && oi < i)) { v = ov; i = oi; }
}

template <int NCOLS>
__global__ void __launch_bounds__(128) argmax_rows_kernel(
    const float* __restrict__ W, int* __restrict__ dest)
{
    const int row = blockIdx.x;
    const float4* __restrict__ r4 =
        reinterpret_cast<const float4*>(W + (size_t)row * NCOLS);
    const int n4 = NCOLS / 4;

    float best = -CUDART_INF_F;
    int   bidx = 0;

    // Strided float4 loop: per-thread index order is increasing, and strict '>'
    // keeps the earliest index among equal values within a thread.
    for (int i = threadIdx.x; i < n4; i += 128) {
        float4 v = r4[i];
        int base = i * 4;
        if (v.x > best) { best = v.x; bidx = base;     }
        if (v.y > best) { best = v.y; bidx = base + 1; }
        if (v.z > best) { best = v.z; bidx = base + 2; }
        if (v.w > best) { best = v.w; bidx = base + 3; }
    }

    // Warp reduction
    #pragma unroll
    for (int off = 16; off > 0; off >>= 1) {
        float ov = __shfl_down_sync(0xFFFFFFFFu, best, off);
        int   oi = __shfl_down_sync(0xFFFFFFFFu, bidx, off);
        amax_combine(best, bidx, ov, oi);
    }

    // Cross-warp reduction (4 warps)
    __shared__ float s_val[4];
    __shared__ int   s_idx[4];
    const int lane = threadIdx.x & 31;
    const int wid  = threadIdx.x >> 5;
    if (lane == 0) { s_val[wid] = best; s_idx[wid] = bidx; }
    __syncthreads();
    if (threadIdx.x == 0) {
        float v = s_val[0]; int i = s_idx[0];
        amax_combine(v, i, s_val[1], s_idx[1]);
        amax_combine(v, i, s_val[2], s_idx[2]);
        amax_combine(v, i, s_val[3], s_idx[3]);
        dest[row] = i;
    }
}

// ---------------------------------------------------------------------------
// Compose the three routing tables: route[s] = dest3[dest2[dest1[s]]]
// ---------------------------------------------------------------------------
__global__ void compose_kernel() {
    int s = blockIdx.x * blockDim.x + threadIdx.x;
    if (s < N_IN) {
        g_route[s] = g_dest3[g_dest2[g_dest1[s]]];
    }
}

// ---------------------------------------------------------------------------
// Scatter: one block per batch. Accumulate counts into a 1024-entry shared
// int array via atomics, then write the float output row.
// ---------------------------------------------------------------------------
__global__ void __launch_bounds__(256) scatter_kernel(
    const int* __restrict__ x, float* __restrict__ out)
{
    __shared__ int acc[N_OUT];
    const int b = blockIdx.x;

    #pragma unroll
    for (int i = threadIdx.x; i < N_OUT; i += 256) acc[i] = 0;
    __syncthreads();

    const int4* __restrict__ xb4 =
        reinterpret_cast<const int4*>(x + (size_t)b * N_IN);
    #pragma unroll 4
    for (int i = threadIdx.x; i < N_IN / 4; i += 256) {
        int4 v = xb4[i];
        int s = i * 4;
        atomicAdd(&acc[g_route[s    ]], v.x);
        atomicAdd(&acc[g_route[s + 1]], v.y);
        atomicAdd(&acc[g_route[s + 2]], v.z);
        atomicAdd(&acc[g_route[s + 3]], v.w);
    }
    __syncthreads();

    float* __restrict__ ob = out + (size_t)b * N_OUT;
    #pragma unroll
    for (int i = threadIdx.x; i < N_OUT; i += 256)
        ob[i] = (float)acc[i];
}

// ---------------------------------------------------------------------------
// Launch
// ---------------------------------------------------------------------------
extern "C" void kernel_launch(void* const* d_in, const int* in_sizes, int n_in,
                              void* d_out, int out_size)
{
    const int*   x  = (const int*)d_in[0];
    const float* W1 = (const float*)d_in[1];
    const float* W2 = (const float*)d_in[2];
    const float* W3 = (const float*)d_in[3];
    float* out = (float*)d_out;

    int *dest1, *dest2, *dest3;
    cudaGetSymbolAddress((void**)&dest1, g_dest1);
    cudaGetSymbolAddress((void**)&dest2, g_dest2);
    cudaGetSymbolAddress((void**)&dest3, g_dest3);

    argmax_rows_kernel<N_MID><<<N_IN, 128>>>(W1, dest1);
    argmax_rows_kernel<N_MID><<<N_MID, 128>>>(W2, dest2);
    argmax_rows_kernel<N_OUT><<<N_MID, 128>>>(W3, dest3);
    compose_kernel<<<N_IN / 256, 256>>>();
    scatter_kernel<<<B, 256>>>(x, out);
}

// round 4
// speedup vs baseline: 1.3039x; 1.3039x over previous
#include <cuda_runtime.h>
#include <cuda_bf16.h>
#include <math_constants.h>

#define B        256
#define N_IN     4096
#define N_MID    4096
#define N_OUT    1024

// Routing tables (device globals — no allocation allowed)
__device__ int g_dest1[N_IN];
__device__ int g_dest2[N_MID];
__device__ int g_dest3[N_MID];   // W3 has 4096 rows

__device__ __forceinline__ void amax_combine(float& v, int& i, float ov, int oi) {
    if (ov > v || (ov == v && oi < i)) { v = ov; i = oi; }
}

__device__ __forceinline__ void proc4(const float4& v, int base, float& best, int& bidx) {
    if (v.x > best) { best = v.x; bidx = base;     }
    if (v.y > best) { best = v.y; bidx = base + 1; }
    if (v.z > best) { best = v.z; bidx = base + 2; }
    if (v.w > best) { best = v.w; bidx = base + 3; }
}

// ---------------------------------------------------------------------------
// One fused argmax launch for all three weight matrices.
// Blocks [0,4096)     -> W1 rows (4096 cols)
// Blocks [4096,8192)  -> W2 rows (4096 cols)
// Blocks [8192,12288) -> W3 rows (1024 cols)
// 256 threads/block; loads batched before compares for MLP.
// ---------------------------------------------------------------------------
__global__ void __launch_bounds__(256) argmax_all_kernel(
    const float* __restrict__ W1, const float* __restrict__ W2,
    const float* __restrict__ W3)
{
    const int bid = blockIdx.x;
    const int tid = threadIdx.x;

    const float* W;
    int* dest;
    int row;
    bool wide;           // 4096 cols vs 1024 cols
    if (bid < N_IN) {
        W = W1; dest = g_dest1; row = bid;          wide = true;
    } else if (bid < 2 * N_IN) {
        W = W2; dest = g_dest2; row = bid - N_IN;   wide = true;
    } else {
        W = W3; dest = g_dest3; row = bid - 2*N_IN; wide = false;
    }

    float best = -CUDART_INF_F;
    int   bidx = 0;

    if (wide) {
        const float4* __restrict__ r4 =
            reinterpret_cast<const float4*>(W + (size_t)row * N_MID);
        // Batch all 4 loads first (front-batched MLP), then compare in
        // increasing index order (strict '>' keeps earliest index).
        float4 a = r4[tid];
        float4 b = r4[tid + 256];
        float4 c = r4[tid + 512];
        float4 d = r4[tid + 768];
        proc4(a, (tid      ) * 4, best, bidx);
        proc4(b, (tid + 256) * 4, best, bidx);
        proc4(c, (tid + 512) * 4, best, bidx);
        proc4(d, (tid + 768) * 4, best, bidx);
    } else {
        const float4* __restrict__ r4 =
            reinterpret_cast<const float4*>(W + (size_t)row * N_OUT);
        float4 a = r4[tid];
        proc4(a, tid * 4, best, bidx);
    }

    // Warp reduction (tie -> smaller index)
    #pragma unroll
    for (int off = 16; off > 0; off >>= 1) {
        float ov = __shfl_down_sync(0xFFFFFFFFu, best, off);
        int   oi = __shfl_down_sync(0xFFFFFFFFu, bidx, off);
        amax_combine(best, bidx, ov, oi);
    }

    // Cross-warp reduction (8 warps)
    __shared__ float s_val[8];
    __shared__ int   s_idx[8];
    const int lane = tid & 31;
    const int wid  = tid >> 5;
    if (lane == 0) { s_val[wid] = best; s_idx[wid] = bidx; }
    __syncthreads();
    if (tid == 0) {
        float v = s_val[0]; int i = s_idx[0];
        #pragma unroll
        for (int w = 1; w < 8; w++) amax_combine(v, i, s_val[w], s_idx[w]);
        dest[row] = i;
    }
}

// ---------------------------------------------------------------------------
// Fused compose + scatter. One block per batch. The route chain
// dest3[dest2[dest1[s]]] is computed inline: the 48KB of tables sit in L2,
// and 4 independent chains per iteration give enough MLP to hide latency.
// ---------------------------------------------------------------------------
__global__ void __launch_bounds__(256) scatter_kernel(
    const int* __restrict__ x, float* __restrict__ out)
{
    __shared__ int acc[N_OUT];
    const int b   = blockIdx.x;
    const int tid = threadIdx.x;

    #pragma unroll
    for (int i = tid; i < N_OUT; i += 256) acc[i] = 0;
    __syncthreads();

    const int4* __restrict__ xb4 =
        reinterpret_cast<const int4*>(x + (size_t)b * N_IN);
    const int4* __restrict__ d1_4 = reinterpret_cast<const int4*>(g_dest1);

    #pragma unroll
    for (int it = 0; it < N_IN / 4 / 256; ++it) {
        const int i = tid + it * 256;
        int4 v  = xb4[i];
        int4 d1 = d1_4[i];          // contiguous: dest1[4i..4i+3]
        int a0 = g_dest2[d1.x];
        int a1 = g_dest2[d1.y];
        int a2 = g_dest2[d1.z];
        int a3 = g_dest2[d1.w];
        int f0 = g_dest3[a0];
        int f1 = g_dest3[a1];
        int f2 = g_dest3[a2];
        int f3 = g_dest3[a3];
        atomicAdd(&acc[f0], v.x);
        atomicAdd(&acc[f1], v.y);
        atomicAdd(&acc[f2], v.z);
        atomicAdd(&acc[f3], v.w);
    }
    __syncthreads();

    float* __restrict__ ob = out + (size_t)b * N_OUT;
    #pragma unroll
    for (int i = tid; i < N_OUT; i += 256)
        ob[i] = (float)acc[i];
}

// ---------------------------------------------------------------------------
extern "C" void kernel_launch(void* const* d_in, const int* in_sizes, int n_in,
                              void* d_out, int out_size)
{
    const int*   x  = (const int*)d_in[0];
    const float* W1 = (const float*)d_in[1];
    const float* W2 = (const float*)d_in[2];
    const float* W3 = (const float*)d_in[3];
    float* out = (float*)d_out;

    argmax_all_kernel<<<3 * N_IN, 256>>>(W1, W2, W3);
    scatter_kernel<<<B, 256>>>(x, out);
}